// round 16
// baseline (speedup 1.0000x reference)
#include <cuda_runtime.h>
#include <cuda_bf16.h>
#include <math.h>
#include <stdint.h>

#define D_MODEL 1024
#define NHEAD 16
#define HEAD_DIM 64
#define MLP_DIM 4096
#define BATCH 2
#define SEQ 2048
#define ROWS (BATCH * SEQ)   // 4096

// ---------------- scratch buffers ----------------
__device__ float g_x[ROWS * D_MODEL];
__device__ float g_q[ROWS * D_MODEL];
__device__ float g_k[ROWS * D_MODEL];
__device__ float g_v[ROWS * D_MODEL];
__device__ float g_att[ROWS * D_MODEL];
__device__ float g_mlpin[ROWS * D_MODEL];
__device__ float g_ln2[ROWS * D_MODEL];
__device__ float g_h[ROWS * MLP_DIM];
// rna-rounded weight copies
__device__ float g_rwq[D_MODEL * D_MODEL];
__device__ float g_rwk[D_MODEL * D_MODEL];
__device__ float g_rwv[D_MODEL * D_MODEL];
__device__ float g_rwo[D_MODEL * D_MODEL];
__device__ float g_rw2[D_MODEL * MLP_DIM];
__device__ float g_rw3[MLP_DIM * D_MODEL];

// ---------------- helpers ----------------
__device__ __forceinline__ float gelu_exact(float x) {
    return 0.5f * x * (1.0f + erff(x * 0.70710678118654752f));
}
__device__ __forceinline__ float to_tf32(float x) {
    uint32_t r;
    asm("cvt.rna.tf32.f32 %0, %1;" : "=r"(r) : "f"(x));
    return __uint_as_float(r);
}
__device__ __forceinline__ void mma_tf32(float* d, const uint32_t* a, const uint32_t* b) {
    asm volatile(
        "mma.sync.aligned.m16n8k8.row.col.f32.tf32.tf32.f32 "
        "{%0,%1,%2,%3}, {%4,%5,%6,%7}, {%8,%9}, {%0,%1,%2,%3};"
        : "+f"(d[0]), "+f"(d[1]), "+f"(d[2]), "+f"(d[3])
        : "r"(a[0]), "r"(a[1]), "r"(a[2]), "r"(a[3]), "r"(b[0]), "r"(b[1]));
}
__device__ __forceinline__ uint32_t smem_u32(const void* p) {
    uint32_t a;
    asm("{ .reg .u64 t; cvta.to.shared.u64 t, %1; cvt.u32.u64 %0, t; }" : "=r"(a) : "l"(p));
    return a;
}
__device__ __forceinline__ void cp16(float* dst_smem, const float* src) {
    uint32_t d = smem_u32(dst_smem);
    asm volatile("cp.async.ca.shared.global [%0], [%1], 16;" :: "r"(d), "l"(src));
}
__device__ __forceinline__ void cp_commit() {
    asm volatile("cp.async.commit_group;" ::: "memory");
}
__device__ __forceinline__ void cp_wait1() {
    asm volatile("cp.async.wait_group 1;" ::: "memory");
}

// ---------------- weight rounding (rna tf32) ----------------
__global__ __launch_bounds__(256) void round_w(const float* __restrict__ src,
                                               float* __restrict__ dst, int n4) {
    int i = blockIdx.x * 256 + threadIdx.x;
    if (i < n4) {
        float4 v = ((const float4*)src)[i];
        v.x = to_tf32(v.x); v.y = to_tf32(v.y);
        v.z = to_tf32(v.z); v.w = to_tf32(v.w);
        ((float4*)dst)[i] = v;
    }
}

// ---------------- LayerNorm (emits tf32-rounded output) ----------------
__global__ __launch_bounds__(256) void ln_kernel(const float* __restrict__ x,
                                                 const float* __restrict__ g,
                                                 const float* __restrict__ b,
                                                 float* __restrict__ out) {
    __shared__ float red[16];
    __shared__ float stats[2];
    int row = blockIdx.x;
    int tid = threadIdx.x;
    const float4* xr = (const float4*)(x + (size_t)row * D_MODEL);
    float4 v = xr[tid];
    float s  = v.x + v.y + v.z + v.w;
    float sq = v.x * v.x + v.y * v.y + v.z * v.z + v.w * v.w;
    #pragma unroll
    for (int o = 16; o > 0; o >>= 1) {
        s  += __shfl_xor_sync(0xffffffffu, s, o);
        sq += __shfl_xor_sync(0xffffffffu, sq, o);
    }
    int warp = tid >> 5, lane = tid & 31;
    if (lane == 0) { red[warp] = s; red[warp + 8] = sq; }
    __syncthreads();
    if (tid == 0) {
        float ts = 0.f, tq = 0.f;
        #pragma unroll
        for (int i = 0; i < 8; i++) { ts += red[i]; tq += red[i + 8]; }
        float mean = ts * (1.0f / D_MODEL);
        float var  = tq * (1.0f / D_MODEL) - mean * mean;
        stats[0] = mean;
        stats[1] = rsqrtf(var + 1e-5f);
    }
    __syncthreads();
    float mean = stats[0], inv = stats[1];
    const float4* gr = (const float4*)g;
    const float4* br = (const float4*)b;
    float4 gv = gr[tid], bv = br[tid];
    float4 ov;
    ov.x = to_tf32((v.x - mean) * inv * gv.x + bv.x);
    ov.y = to_tf32((v.y - mean) * inv * gv.y + bv.y);
    ov.z = to_tf32((v.z - mean) * inv * gv.z + bv.z);
    ov.w = to_tf32((v.w - mean) * inv * gv.w + bv.w);
    ((float4*)(out + (size_t)row * D_MODEL))[tid] = ov;
}

// ---------------- tf32 GEMM: 128x256 block, 64x64 warp, 3-stage cp.async ----------
#define ASTRIDE 36
#define BSTRIDE 264
#define ABUF (128 * ASTRIDE)          // 4608 floats
#define BBUF (32 * BSTRIDE)           // 8448 floats
#define STG (ABUF + BBUF)             // 13056 floats
#define GEMM_SMEM (3 * STG * 4)       // 156672 bytes

// EPI: 0 = none, 1 = +res, 2 = +bias gelu (tf32 out), 3 = +bias +res
template <int EPI>
__global__ __launch_bounds__(256, 1) void gemm_tf32(
    const float* __restrict__ A, const float* __restrict__ B,
    const float* __restrict__ bias, const float* __restrict__ res,
    float* __restrict__ C, int M, int N, int K)
{
    extern __shared__ float smem[];

    int tid = threadIdx.x;
    int lane = tid & 31, wid = tid >> 5;
    int g = lane >> 2, l = lane & 3;
    int wm = (wid & 1) * 64;
    int wn = (wid >> 1) * 64;

    int bx = blockIdx.x, by = blockIdx.y;

    int ar = tid >> 1;
    int ac = (tid & 1) * 16;
    int br = tid >> 3;
    int bc = (tid & 7) * 32;

    const float* Ag = A + (size_t)(by * 128 + ar) * K + ac;
    const float* Bg = B + (size_t)br * N + bx * 256 + bc;

    float acc[4][8][4];
    #pragma unroll
    for (int mi = 0; mi < 4; mi++)
        #pragma unroll
        for (int nj = 0; nj < 8; nj++)
            #pragma unroll
            for (int r = 0; r < 4; r++) acc[mi][nj][r] = 0.f;

    int nIter = K / 32;

    #pragma unroll
    for (int s = 0; s < 2; s++) {
        float* as = smem + s * STG + ar * ASTRIDE + ac;
        float* bs = smem + s * STG + ABUF + br * BSTRIDE + bc;
        #pragma unroll
        for (int i = 0; i < 4; i++) cp16(as + i * 4, Ag + s * 32 + i * 4);
        #pragma unroll
        for (int i = 0; i < 8; i++) cp16(bs + i * 4, Bg + (size_t)(s * 32) * N + i * 4);
        cp_commit();
    }

    for (int t = 0; t < nIter; t++) {
        cp_wait1();
        __syncthreads();

        if (t + 2 < nIter) {
            int s = (t + 2) % 3;
            int k0 = (t + 2) * 32;
            float* as = smem + s * STG + ar * ASTRIDE + ac;
            float* bs = smem + s * STG + ABUF + br * BSTRIDE + bc;
            #pragma unroll
            for (int i = 0; i < 4; i++) cp16(as + i * 4, Ag + k0 + i * 4);
            #pragma unroll
            for (int i = 0; i < 8; i++) cp16(bs + i * 4, Bg + (size_t)k0 * N + i * 4);
            cp_commit();
        }

        const float* ab = smem + (t % 3) * STG;
        const float* bb = ab + ABUF;
        #pragma unroll
        for (int ks = 0; ks < 4; ks++) {
            int k8 = ks * 8;
            uint32_t af[4][4], bf[8][2];
            #pragma unroll
            for (int mi = 0; mi < 4; mi++) {
                const float* p = ab + (wm + mi * 16 + g) * ASTRIDE + k8 + l;
                af[mi][0] = __float_as_uint(p[0]);
                af[mi][1] = __float_as_uint(p[8 * ASTRIDE]);
                af[mi][2] = __float_as_uint(p[4]);
                af[mi][3] = __float_as_uint(p[8 * ASTRIDE + 4]);
            }
            #pragma unroll
            for (int nj = 0; nj < 8; nj++) {
                const float* p = bb + (k8 + l) * BSTRIDE + wn + nj * 8 + g;
                bf[nj][0] = __float_as_uint(p[0]);
                bf[nj][1] = __float_as_uint(p[4 * BSTRIDE]);
            }
            #pragma unroll
            for (int mi = 0; mi < 4; mi++)
                #pragma unroll
                for (int nj = 0; nj < 8; nj++)
                    mma_tf32(acc[mi][nj], af[mi], bf[nj]);
        }
    }

    int row0 = by * 128 + wm;
    int col0 = bx * 256 + wn;
    #pragma unroll
    for (int mi = 0; mi < 4; mi++) {
        int r = row0 + mi * 16 + g;
        #pragma unroll
        for (int nj = 0; nj < 8; nj++) {
            int cc = col0 + nj * 8 + 2 * l;
            float v0 = acc[mi][nj][0], v1 = acc[mi][nj][1];
            float v2 = acc[mi][nj][2], v3 = acc[mi][nj][3];
            if (EPI == 2 || EPI == 3) {
                float b0 = bias[cc], b1 = bias[cc + 1];
                v0 += b0; v1 += b1; v2 += b0; v3 += b1;
            }
            if (EPI == 2) {
                v0 = to_tf32(gelu_exact(v0)); v1 = to_tf32(gelu_exact(v1));
                v2 = to_tf32(gelu_exact(v2)); v3 = to_tf32(gelu_exact(v3));
            }
            if (EPI == 1 || EPI == 3) {
                const float* r0p = res + (size_t)r * N + cc;
                const float* r1p = res + (size_t)(r + 8) * N + cc;
                v0 += r0p[0]; v1 += r0p[1];
                v2 += r1p[0]; v3 += r1p[1];
            }
            *(float2*)&C[(size_t)r * N + cc] = make_float2(v0, v1);
            *(float2*)&C[(size_t)(r + 8) * N + cc] = make_float2(v2, v3);
        }
    }
}

// ---------------- fused QKV GEMM with RoPE epilogue ----------------
// grid.x = 12: mat = bx>>2 (0=q,1=k,2=v), nx = bx&3.
__global__ __launch_bounds__(256, 1) void qkv_gemm(
    const float* __restrict__ A,
    const float* __restrict__ Wq, const float* __restrict__ Wk,
    const float* __restrict__ Wv,
    float* __restrict__ Oq, float* __restrict__ Ok, float* __restrict__ Ov)
{
    extern __shared__ float smem[];

    const int N = D_MODEL, K = D_MODEL;
    int tid = threadIdx.x;
    int lane = tid & 31, wid = tid >> 5;
    int g = lane >> 2, l = lane & 3;
    int wm = (wid & 1) * 64;
    int wn = (wid >> 1) * 64;

    int mat = blockIdx.x >> 2;
    int nx  = blockIdx.x & 3;
    int by  = blockIdx.y;
    const float* B = (mat == 0) ? Wq : (mat == 1) ? Wk : Wv;
    float* C = (mat == 0) ? Oq : (mat == 1) ? Ok : Ov;

    int ar = tid >> 1;
    int ac = (tid & 1) * 16;
    int br = tid >> 3;
    int bc = (tid & 7) * 32;

    const float* Ag = A + (size_t)(by * 128 + ar) * K + ac;
    const float* Bg = B + (size_t)br * N + nx * 256 + bc;

    float acc[4][8][4];
    #pragma unroll
    for (int mi = 0; mi < 4; mi++)
        #pragma unroll
        for (int nj = 0; nj < 8; nj++)
            #pragma unroll
            for (int r = 0; r < 4; r++) acc[mi][nj][r] = 0.f;

    const int nIter = K / 32;

    #pragma unroll
    for (int s = 0; s < 2; s++) {
        float* as = smem + s * STG + ar * ASTRIDE + ac;
        float* bs = smem + s * STG + ABUF + br * BSTRIDE + bc;
        #pragma unroll
        for (int i = 0; i < 4; i++) cp16(as + i * 4, Ag + s * 32 + i * 4);
        #pragma unroll
        for (int i = 0; i < 8; i++) cp16(bs + i * 4, Bg + (size_t)(s * 32) * N + i * 4);
        cp_commit();
    }

    for (int t = 0; t < nIter; t++) {
        cp_wait1();
        __syncthreads();

        if (t + 2 < nIter) {
            int s = (t + 2) % 3;
            int k0 = (t + 2) * 32;
            float* as = smem + s * STG + ar * ASTRIDE + ac;
            float* bs = smem + s * STG + ABUF + br * BSTRIDE + bc;
            #pragma unroll
            for (int i = 0; i < 4; i++) cp16(as + i * 4, Ag + k0 + i * 4);
            #pragma unroll
            for (int i = 0; i < 8; i++) cp16(bs + i * 4, Bg + (size_t)k0 * N + i * 4);
            cp_commit();
        }

        const float* ab = smem + (t % 3) * STG;
        const float* bb = ab + ABUF;
        #pragma unroll
        for (int ks = 0; ks < 4; ks++) {
            int k8 = ks * 8;
            uint32_t af[4][4], bf[8][2];
            #pragma unroll
            for (int mi = 0; mi < 4; mi++) {
                const float* p = ab + (wm + mi * 16 + g) * ASTRIDE + k8 + l;
                af[mi][0] = __float_as_uint(p[0]);
                af[mi][1] = __float_as_uint(p[8 * ASTRIDE]);
                af[mi][2] = __float_as_uint(p[4]);
                af[mi][3] = __float_as_uint(p[8 * ASTRIDE + 4]);
            }
            #pragma unroll
            for (int nj = 0; nj < 8; nj++) {
                const float* p = bb + (k8 + l) * BSTRIDE + wn + nj * 8 + g;
                bf[nj][0] = __float_as_uint(p[0]);
                bf[nj][1] = __float_as_uint(p[4 * BSTRIDE]);
            }
            #pragma unroll
            for (int mi = 0; mi < 4; mi++)
                #pragma unroll
                for (int nj = 0; nj < 8; nj++)
                    mma_tf32(acc[mi][nj], af[mi], bf[nj]);
        }
    }

    int row0 = by * 128 + wm;
    int col0 = nx * 256 + wn;
    bool rope = (mat < 2);
    #pragma unroll
    for (int mi = 0; mi < 4; mi++) {
        int r = row0 + mi * 16 + g;
        int t0 = r & (SEQ - 1);
        #pragma unroll
        for (int nj = 0; nj < 8; nj++) {
            int cc = col0 + nj * 8 + 2 * l;
            float v0 = acc[mi][nj][0], v1 = acc[mi][nj][1];
            float v2 = acc[mi][nj][2], v3 = acc[mi][nj][3];
            if (rope) {
                int pi = (cc & 63) >> 1;
                float invf = exp2f(-0.41524101186f * (float)pi);
                float a0 = (float)t0 * invf;
                float a1 = (float)(t0 + 8) * invf;
                float c0, s0, c1, s1;
                sincosf(a0, &s0, &c0);
                sincosf(a1, &s1, &c1);
                float n0 = v0 * c0 - v1 * s0;
                float n1 = v1 * c0 + v0 * s0;
                float n2 = v2 * c1 - v3 * s1;
                float n3 = v3 * c1 + v2 * s1;
                v0 = n0; v1 = n1; v2 = n2; v3 = n3;
            }
            *(float2*)&C[(size_t)r * D_MODEL + cc] = make_float2(v0, v1);
            *(float2*)&C[(size_t)(r + 8) * D_MODEL + cc] = make_float2(v2, v3);
        }
    }
}

// ---------------- MMA flash attention (tf32) — R6 version + tf32-rounded output ----
#define KSTR 68
#define ATT_SMEM ((64 * KSTR + 64 * KSTR + 128 * KSTR) * 4)

__global__ __launch_bounds__(256) void attn_mma(const float* __restrict__ q,
                                                const float* __restrict__ k,
                                                const float* __restrict__ v,
                                                float* __restrict__ out) {
    extern __shared__ float sm[];
    float* Ks = sm;
    float* Vs = sm + 64 * KSTR;
    float* Ps = sm + 128 * KSTR;

    int tid = threadIdx.x;
    int lane = tid & 31, wid = tid >> 5;
    int g = lane >> 2, l = lane & 3;
    int wm = wid * 16;

    int qtile = blockIdx.x;
    int bh = blockIdx.y;
    int b = bh >> 4, h = bh & 15;
    int hoff = h * HEAD_DIM;
    int qrow0 = b * SEQ + qtile * 128;

    for (int i = tid; i < 128 * 16; i += 256) {
        int r = i >> 4, d4 = (i & 15) * 4;
        float4 qv = *(const float4*)(q + (size_t)(qrow0 + r) * D_MODEL + hoff + d4);
        float4 t;
        t.x = to_tf32(qv.x * 0.125f); t.y = to_tf32(qv.y * 0.125f);
        t.z = to_tf32(qv.z * 0.125f); t.w = to_tf32(qv.w * 0.125f);
        *(float4*)(Ps + r * KSTR + d4) = t;
    }
    __syncthreads();
    uint32_t qf[8][4];
    #pragma unroll
    for (int ks = 0; ks < 8; ks++) {
        const float* p = Ps + (wm + g) * KSTR + ks * 8 + l;
        qf[ks][0] = __float_as_uint(p[0]);
        qf[ks][1] = __float_as_uint(p[8 * KSTR]);
        qf[ks][2] = __float_as_uint(p[4]);
        qf[ks][3] = __float_as_uint(p[8 * KSTR + 4]);
    }

    float oa[8][4];
    #pragma unroll
    for (int nj = 0; nj < 8; nj++)
        #pragma unroll
        for (int r = 0; r < 4; r++) oa[nj][r] = 0.f;
    float m0 = -1e30f, m1 = -1e30f, ls0 = 0.f, ls1 = 0.f;

    for (int kt = 0; kt < SEQ / 64; kt++) {
        __syncthreads();
        for (int i = tid; i < 64 * 16; i += 256) {
            int r = i >> 4, d4 = (i & 15) * 4;
            size_t gi = (size_t)(b * SEQ + kt * 64 + r) * D_MODEL + hoff + d4;
            float4 kv = *(const float4*)(k + gi);
            float4 tk;
            tk.x = to_tf32(kv.x); tk.y = to_tf32(kv.y);
            tk.z = to_tf32(kv.z); tk.w = to_tf32(kv.w);
            *(float4*)(Ks + r * KSTR + d4) = tk;
            float4 vv = *(const float4*)(v + gi);
            float4 tv;
            tv.x = to_tf32(vv.x); tv.y = to_tf32(vv.y);
            tv.z = to_tf32(vv.z); tv.w = to_tf32(vv.w);
            *(float4*)(Vs + r * KSTR + d4) = tv;
        }
        __syncthreads();

        float sa[8][4];
        #pragma unroll
        for (int nj = 0; nj < 8; nj++)
            #pragma unroll
            for (int r = 0; r < 4; r++) sa[nj][r] = 0.f;
        #pragma unroll
        for (int ks = 0; ks < 8; ks++) {
            int k8 = ks * 8;
            #pragma unroll
            for (int nj = 0; nj < 8; nj++) {
                const float* p = Ks + (nj * 8 + g) * KSTR + k8 + l;
                uint32_t bf[2];
                bf[0] = __float_as_uint(p[0]);
                bf[1] = __float_as_uint(p[4]);
                mma_tf32(sa[nj], qf[ks], bf);
            }
        }

        float mx0 = -1e30f, mx1 = -1e30f;
        #pragma unroll
        for (int nj = 0; nj < 8; nj++) {
            mx0 = fmaxf(mx0, fmaxf(sa[nj][0], sa[nj][1]));
            mx1 = fmaxf(mx1, fmaxf(sa[nj][2], sa[nj][3]));
        }
        mx0 = fmaxf(mx0, __shfl_xor_sync(0xffffffffu, mx0, 1));
        mx0 = fmaxf(mx0, __shfl_xor_sync(0xffffffffu, mx0, 2));
        mx1 = fmaxf(mx1, __shfl_xor_sync(0xffffffffu, mx1, 1));
        mx1 = fmaxf(mx1, __shfl_xor_sync(0xffffffffu, mx1, 2));
        float nm0 = fmaxf(m0, mx0), nm1 = fmaxf(m1, mx1);
        float sc0 = __expf(m0 - nm0), sc1 = __expf(m1 - nm1);
        m0 = nm0; m1 = nm1;
        ls0 *= sc0; ls1 *= sc1;
        #pragma unroll
        for (int nj = 0; nj < 8; nj++) {
            oa[nj][0] *= sc0; oa[nj][1] *= sc0;
            oa[nj][2] *= sc1; oa[nj][3] *= sc1;
        }

        float* pw0 = Ps + (wm + g) * KSTR + 2 * l;
        float* pw1 = Ps + (wm + g + 8) * KSTR + 2 * l;
        #pragma unroll
        for (int nj = 0; nj < 8; nj++) {
            float p0 = __expf(sa[nj][0] - m0);
            float p1 = __expf(sa[nj][1] - m0);
            float p2 = __expf(sa[nj][2] - m1);
            float p3 = __expf(sa[nj][3] - m1);
            ls0 += p0 + p1;
            ls1 += p2 + p3;
            *(float2*)(pw0 + nj * 8) = make_float2(to_tf32(p0), to_tf32(p1));
            *(float2*)(pw1 + nj * 8) = make_float2(to_tf32(p2), to_tf32(p3));
        }
        __syncwarp();

        #pragma unroll
        for (int ks = 0; ks < 8; ks++) {
            int k8 = ks * 8;
            uint32_t pf[4];
            const float* pp = Ps + (wm + g) * KSTR + k8 + l;
            pf[0] = __float_as_uint(pp[0]);
            pf[1] = __float_as_uint(pp[8 * KSTR]);
            pf[2] = __float_as_uint(pp[4]);
            pf[3] = __float_as_uint(pp[8 * KSTR + 4]);
            #pragma unroll
            for (int nj = 0; nj < 8; nj++) {
                const float* vp = Vs + (k8 + l) * KSTR + nj * 8 + g;
                uint32_t vf[2];
                vf[0] = __float_as_uint(vp[0]);
                vf[1] = __float_as_uint(vp[4 * KSTR]);
                mma_tf32(oa[nj], pf, vf);
            }
        }
    }

    ls0 += __shfl_xor_sync(0xffffffffu, ls0, 1);
    ls0 += __shfl_xor_sync(0xffffffffu, ls0, 2);
    ls1 += __shfl_xor_sync(0xffffffffu, ls1, 1);
    ls1 += __shfl_xor_sync(0xffffffffu, ls1, 2);
    float inv0 = 1.0f / ls0, inv1 = 1.0f / ls1;

    int r0 = qrow0 + wm + g;
    #pragma unroll
    for (int nj = 0; nj < 8; nj++) {
        int cc = hoff + nj * 8 + 2 * l;
        *(float2*)&out[(size_t)r0 * D_MODEL + cc] =
            make_float2(to_tf32(oa[nj][0] * inv0), to_tf32(oa[nj][1] * inv0));
        *(float2*)&out[(size_t)(r0 + 8) * D_MODEL + cc] =
            make_float2(to_tf32(oa[nj][2] * inv1), to_tf32(oa[nj][3] * inv1));
    }
}

// ---------------- launch ----------------
extern "C" void kernel_launch(void* const* d_in, const int* in_sizes, int n_in,
                              void* d_out, int out_size) {
    const float* inputs = (const float*)d_in[0];
    const float* ln1_g  = (const float*)d_in[1];
    const float* ln1_b  = (const float*)d_in[2];
    const float* Wq     = (const float*)d_in[3];
    const float* Wk     = (const float*)d_in[4];
    const float* Wv     = (const float*)d_in[5];
    const float* Wo     = (const float*)d_in[6];
    const float* ln2_g  = (const float*)d_in[7];
    const float* ln2_b  = (const float*)d_in[8];
    const float* Wfc2   = (const float*)d_in[9];
    const float* bfc2   = (const float*)d_in[10];
    const float* Wfc3   = (const float*)d_in[11];
    const float* bfc3   = (const float*)d_in[12];
    float* out = (float*)d_out;

    float *px, *pq, *pk, *pv, *patt, *pmlp, *pln2, *ph;
    float *rwq, *rwk, *rwv, *rwo, *rw2, *rw3;
    cudaGetSymbolAddress((void**)&px,   g_x);
    cudaGetSymbolAddress((void**)&pq,   g_q);
    cudaGetSymbolAddress((void**)&pk,   g_k);
    cudaGetSymbolAddress((void**)&pv,   g_v);
    cudaGetSymbolAddress((void**)&patt, g_att);
    cudaGetSymbolAddress((void**)&pmlp, g_mlpin);
    cudaGetSymbolAddress((void**)&pln2, g_ln2);
    cudaGetSymbolAddress((void**)&ph,   g_h);
    cudaGetSymbolAddress((void**)&rwq,  g_rwq);
    cudaGetSymbolAddress((void**)&rwk,  g_rwk);
    cudaGetSymbolAddress((void**)&rwv,  g_rwv);
    cudaGetSymbolAddress((void**)&rwo,  g_rwo);
    cudaGetSymbolAddress((void**)&rw2,  g_rw2);
    cudaGetSymbolAddress((void**)&rw3,  g_rw3);

    cudaFuncSetAttribute(gemm_tf32<1>, cudaFuncAttributeMaxDynamicSharedMemorySize, GEMM_SMEM);
    cudaFuncSetAttribute(gemm_tf32<2>, cudaFuncAttributeMaxDynamicSharedMemorySize, GEMM_SMEM);
    cudaFuncSetAttribute(gemm_tf32<3>, cudaFuncAttributeMaxDynamicSharedMemorySize, GEMM_SMEM);
    cudaFuncSetAttribute(qkv_gemm,     cudaFuncAttributeMaxDynamicSharedMemorySize, GEMM_SMEM);
    cudaFuncSetAttribute(attn_mma,     cudaFuncAttributeMaxDynamicSharedMemorySize, ATT_SMEM);

    // 0. round weights to tf32 (rna) once per call
    int n1 = D_MODEL * D_MODEL / 4, n2 = D_MODEL * MLP_DIM / 4;
    round_w<<<(n1 + 255) / 256, 256>>>(Wq,   rwq, n1);
    round_w<<<(n1 + 255) / 256, 256>>>(Wk,   rwk, n1);
    round_w<<<(n1 + 255) / 256, 256>>>(Wv,   rwv, n1);
    round_w<<<(n1 + 255) / 256, 256>>>(Wo,   rwo, n1);
    round_w<<<(n2 + 255) / 256, 256>>>(Wfc2, rw2, n2);
    round_w<<<(n2 + 255) / 256, 256>>>(Wfc3, rw3, n2);

    // 1. x = LN1(inputs)  (tf32-rounded)
    ln_kernel<<<ROWS, 256>>>(inputs, ln1_g, ln1_b, px);

    // 2+3. fused QKV GEMM with RoPE epilogue
    qkv_gemm<<<dim3(12, ROWS / 128), 256, GEMM_SMEM>>>(px, rwq, rwk, rwv, pq, pk, pv);

    // 4. attention (tensor-core flash; tf32-rounded output)
    attn_mma<<<dim3(SEQ / 128, BATCH * NHEAD), 256, ATT_SMEM>>>(pq, pk, pv, patt);

    // 5. mlp_in = attn @ Wo + inputs
    gemm_tf32<1><<<dim3(D_MODEL / 256, ROWS / 128), 256, GEMM_SMEM>>>(
        patt, rwo, nullptr, inputs, pmlp, ROWS, D_MODEL, D_MODEL);

    // 6. ln2 (tf32-rounded)
    ln_kernel<<<ROWS, 256>>>(pmlp, ln2_g, ln2_b, pln2);

    // 7. h = gelu(ln2 @ Wfc2 + bfc2)  (tf32-rounded)
    gemm_tf32<2><<<dim3(MLP_DIM / 256, ROWS / 128), 256, GEMM_SMEM>>>(
        pln2, rw2, bfc2, nullptr, ph, ROWS, MLP_DIM, D_MODEL);

    // 8. out = h @ Wfc3 + bfc3 + mlp_in
    gemm_tf32<3><<<dim3(D_MODEL / 256, ROWS / 128), 256, GEMM_SMEM>>>(
        ph, rw3, bfc3, pmlp, out, ROWS, D_MODEL, MLP_DIM);
}

// round 17
// speedup vs baseline: 1.3000x; 1.3000x over previous
#include <cuda_runtime.h>
#include <cuda_bf16.h>
#include <math.h>
#include <stdint.h>

#define D_MODEL 1024
#define NHEAD 16
#define HEAD_DIM 64
#define MLP_DIM 4096
#define BATCH 2
#define SEQ 2048
#define ROWS (BATCH * SEQ)   // 4096

// ---------------- scratch buffers ----------------
__device__ float g_x[ROWS * D_MODEL];
__device__ float g_q[ROWS * D_MODEL];
__device__ float g_k[ROWS * D_MODEL];
__device__ float g_v[ROWS * D_MODEL];
__device__ float g_att[ROWS * D_MODEL];
__device__ float g_mlpin[ROWS * D_MODEL];
__device__ float g_ln2[ROWS * D_MODEL];
__device__ float g_h[ROWS * MLP_DIM];
// rna-rounded weight copies
__device__ float g_rwq[D_MODEL * D_MODEL];
__device__ float g_rwk[D_MODEL * D_MODEL];
__device__ float g_rwv[D_MODEL * D_MODEL];
__device__ float g_rwo[D_MODEL * D_MODEL];
__device__ float g_rw2[D_MODEL * MLP_DIM];
__device__ float g_rw3[MLP_DIM * D_MODEL];

// ---------------- helpers ----------------
__device__ __forceinline__ float gelu_exact(float x) {
    return 0.5f * x * (1.0f + erff(x * 0.70710678118654752f));
}
__device__ __forceinline__ float to_tf32(float x) {
    uint32_t r;
    asm("cvt.rna.tf32.f32 %0, %1;" : "=r"(r) : "f"(x));
    return __uint_as_float(r);
}
__device__ __forceinline__ void mma_tf32(float* d, const uint32_t* a, const uint32_t* b) {
    asm volatile(
        "mma.sync.aligned.m16n8k8.row.col.f32.tf32.tf32.f32 "
        "{%0,%1,%2,%3}, {%4,%5,%6,%7}, {%8,%9}, {%0,%1,%2,%3};"
        : "+f"(d[0]), "+f"(d[1]), "+f"(d[2]), "+f"(d[3])
        : "r"(a[0]), "r"(a[1]), "r"(a[2]), "r"(a[3]), "r"(b[0]), "r"(b[1]));
}
__device__ __forceinline__ uint32_t smem_u32(const void* p) {
    uint32_t a;
    asm("{ .reg .u64 t; cvta.to.shared.u64 t, %1; cvt.u32.u64 %0, t; }" : "=r"(a) : "l"(p));
    return a;
}
__device__ __forceinline__ void cp16(float* dst_smem, const float* src) {
    uint32_t d = smem_u32(dst_smem);
    asm volatile("cp.async.ca.shared.global [%0], [%1], 16;" :: "r"(d), "l"(src));
}
__device__ __forceinline__ void cp_commit() {
    asm volatile("cp.async.commit_group;" ::: "memory");
}
__device__ __forceinline__ void cp_wait1() {
    asm volatile("cp.async.wait_group 1;" ::: "memory");
}

// ---------------- weight rounding (rna tf32) ----------------
__global__ __launch_bounds__(256) void round_w(const float* __restrict__ src,
                                               float* __restrict__ dst, int n4) {
    int i = blockIdx.x * 256 + threadIdx.x;
    if (i < n4) {
        float4 v = ((const float4*)src)[i];
        v.x = to_tf32(v.x); v.y = to_tf32(v.y);
        v.z = to_tf32(v.z); v.w = to_tf32(v.w);
        ((float4*)dst)[i] = v;
    }
}

// ---------------- LayerNorm (emits tf32-rounded output) ----------------
__global__ __launch_bounds__(256) void ln_kernel(const float* __restrict__ x,
                                                 const float* __restrict__ g,
                                                 const float* __restrict__ b,
                                                 float* __restrict__ out) {
    __shared__ float red[16];
    __shared__ float stats[2];
    int row = blockIdx.x;
    int tid = threadIdx.x;
    const float4* xr = (const float4*)(x + (size_t)row * D_MODEL);
    float4 v = xr[tid];
    float s  = v.x + v.y + v.z + v.w;
    float sq = v.x * v.x + v.y * v.y + v.z * v.z + v.w * v.w;
    #pragma unroll
    for (int o = 16; o > 0; o >>= 1) {
        s  += __shfl_xor_sync(0xffffffffu, s, o);
        sq += __shfl_xor_sync(0xffffffffu, sq, o);
    }
    int warp = tid >> 5, lane = tid & 31;
    if (lane == 0) { red[warp] = s; red[warp + 8] = sq; }
    __syncthreads();
    if (tid == 0) {
        float ts = 0.f, tq = 0.f;
        #pragma unroll
        for (int i = 0; i < 8; i++) { ts += red[i]; tq += red[i + 8]; }
        float mean = ts * (1.0f / D_MODEL);
        float var  = tq * (1.0f / D_MODEL) - mean * mean;
        stats[0] = mean;
        stats[1] = rsqrtf(var + 1e-5f);
    }
    __syncthreads();
    float mean = stats[0], inv = stats[1];
    const float4* gr = (const float4*)g;
    const float4* br = (const float4*)b;
    float4 gv = gr[tid], bv = br[tid];
    float4 ov;
    ov.x = to_tf32((v.x - mean) * inv * gv.x + bv.x);
    ov.y = to_tf32((v.y - mean) * inv * gv.y + bv.y);
    ov.z = to_tf32((v.z - mean) * inv * gv.z + bv.z);
    ov.w = to_tf32((v.w - mean) * inv * gv.w + bv.w);
    ((float4*)(out + (size_t)row * D_MODEL))[tid] = ov;
}

// ------- tf32 GEMM: 128x128 block, 4 warps of 64x64, 3-stage cp.async, 2 CTA/SM ----
#define ASTRIDE 36
#define BSTRIDE 136
#define ABUF (128 * ASTRIDE)          // 4608 floats
#define BBUF (32 * BSTRIDE)           // 4352 floats
#define STG (ABUF + BBUF)             // 8960 floats
#define GEMM_SMEM (3 * STG * 4)       // 107520 bytes

// EPI: 0 = none, 1 = +res, 2 = +bias gelu (tf32 out), 3 = +bias +res
template <int EPI>
__global__ __launch_bounds__(128, 2) void gemm_tf32(
    const float* __restrict__ A, const float* __restrict__ B,
    const float* __restrict__ bias, const float* __restrict__ res,
    float* __restrict__ C, int M, int N, int K)
{
    extern __shared__ float smem[];

    int tid = threadIdx.x;
    int lane = tid & 31, wid = tid >> 5;
    int g = lane >> 2, l = lane & 3;
    int wm = (wid & 1) * 64;
    int wn = (wid >> 1) * 64;

    int bx = blockIdx.x, by = blockIdx.y;

    // staging indices (128 threads)
    int aRow = tid >> 3;          // 0..15 (+16*i)
    int aCol = (tid & 7) * 4;     // float col
    int bRow = tid >> 2;          // 0..31
    int bCol = (tid & 3) * 4;     // float col (+16*i)

    const float* Ag = A + (size_t)(by * 128 + aRow) * K + aCol;
    const float* Bg = B + (size_t)bRow * N + bx * 128 + bCol;

    float acc[4][8][4];
    #pragma unroll
    for (int mi = 0; mi < 4; mi++)
        #pragma unroll
        for (int nj = 0; nj < 8; nj++)
            #pragma unroll
            for (int r = 0; r < 4; r++) acc[mi][nj][r] = 0.f;

    int nIter = K / 32;

    #pragma unroll
    for (int s = 0; s < 2; s++) {
        float* as = smem + s * STG;
        float* bs = smem + s * STG + ABUF;
        #pragma unroll
        for (int i = 0; i < 8; i++)
            cp16(as + (aRow + i * 16) * ASTRIDE + aCol,
                 Ag + (size_t)(i * 16) * K + s * 32);
        #pragma unroll
        for (int i = 0; i < 8; i++)
            cp16(bs + bRow * BSTRIDE + bCol + i * 16,
                 Bg + (size_t)(s * 32) * N + i * 16);
        cp_commit();
    }

    for (int t = 0; t < nIter; t++) {
        cp_wait1();
        __syncthreads();

        if (t + 2 < nIter) {
            int s = (t + 2) % 3;
            int k0 = (t + 2) * 32;
            float* as = smem + s * STG;
            float* bs = smem + s * STG + ABUF;
            #pragma unroll
            for (int i = 0; i < 8; i++)
                cp16(as + (aRow + i * 16) * ASTRIDE + aCol,
                     Ag + (size_t)(i * 16) * K + k0);
            #pragma unroll
            for (int i = 0; i < 8; i++)
                cp16(bs + bRow * BSTRIDE + bCol + i * 16,
                     Bg + (size_t)k0 * N + i * 16);
            cp_commit();
        }

        const float* ab = smem + (t % 3) * STG;
        const float* bb = ab + ABUF;
        #pragma unroll
        for (int ks = 0; ks < 4; ks++) {
            int k8 = ks * 8;
            uint32_t af[4][4], bf[8][2];
            #pragma unroll
            for (int mi = 0; mi < 4; mi++) {
                const float* p = ab + (wm + mi * 16 + g) * ASTRIDE + k8 + l;
                af[mi][0] = __float_as_uint(p[0]);
                af[mi][1] = __float_as_uint(p[8 * ASTRIDE]);
                af[mi][2] = __float_as_uint(p[4]);
                af[mi][3] = __float_as_uint(p[8 * ASTRIDE + 4]);
            }
            #pragma unroll
            for (int nj = 0; nj < 8; nj++) {
                const float* p = bb + (k8 + l) * BSTRIDE + wn + nj * 8 + g;
                bf[nj][0] = __float_as_uint(p[0]);
                bf[nj][1] = __float_as_uint(p[4 * BSTRIDE]);
            }
            #pragma unroll
            for (int mi = 0; mi < 4; mi++)
                #pragma unroll
                for (int nj = 0; nj < 8; nj++)
                    mma_tf32(acc[mi][nj], af[mi], bf[nj]);
        }
    }

    int row0 = by * 128 + wm;
    int col0 = bx * 128 + wn;
    #pragma unroll
    for (int mi = 0; mi < 4; mi++) {
        int r = row0 + mi * 16 + g;
        #pragma unroll
        for (int nj = 0; nj < 8; nj++) {
            int cc = col0 + nj * 8 + 2 * l;
            float v0 = acc[mi][nj][0], v1 = acc[mi][nj][1];
            float v2 = acc[mi][nj][2], v3 = acc[mi][nj][3];
            if (EPI == 2 || EPI == 3) {
                float b0 = bias[cc], b1 = bias[cc + 1];
                v0 += b0; v1 += b1; v2 += b0; v3 += b1;
            }
            if (EPI == 2) {
                v0 = to_tf32(gelu_exact(v0)); v1 = to_tf32(gelu_exact(v1));
                v2 = to_tf32(gelu_exact(v2)); v3 = to_tf32(gelu_exact(v3));
            }
            if (EPI == 1 || EPI == 3) {
                const float* r0p = res + (size_t)r * N + cc;
                const float* r1p = res + (size_t)(r + 8) * N + cc;
                v0 += r0p[0]; v1 += r0p[1];
                v2 += r1p[0]; v3 += r1p[1];
            }
            *(float2*)&C[(size_t)r * N + cc] = make_float2(v0, v1);
            *(float2*)&C[(size_t)(r + 8) * N + cc] = make_float2(v2, v3);
        }
    }
}

// ---------------- fused QKV GEMM with RoPE epilogue ----------------
// grid.x = 24: mat = bx>>3 (0=q,1=k,2=v), nx = bx&7.
__global__ __launch_bounds__(128, 2) void qkv_gemm(
    const float* __restrict__ A,
    const float* __restrict__ Wq, const float* __restrict__ Wk,
    const float* __restrict__ Wv,
    float* __restrict__ Oq, float* __restrict__ Ok, float* __restrict__ Ov)
{
    extern __shared__ float smem[];

    const int N = D_MODEL, K = D_MODEL;
    int tid = threadIdx.x;
    int lane = tid & 31, wid = tid >> 5;
    int g = lane >> 2, l = lane & 3;
    int wm = (wid & 1) * 64;
    int wn = (wid >> 1) * 64;

    int mat = blockIdx.x >> 3;
    int nx  = blockIdx.x & 7;
    int by  = blockIdx.y;
    const float* B = (mat == 0) ? Wq : (mat == 1) ? Wk : Wv;
    float* C = (mat == 0) ? Oq : (mat == 1) ? Ok : Ov;

    int aRow = tid >> 3;
    int aCol = (tid & 7) * 4;
    int bRow = tid >> 2;
    int bCol = (tid & 3) * 4;

    const float* Ag = A + (size_t)(by * 128 + aRow) * K + aCol;
    const float* Bg = B + (size_t)bRow * N + nx * 128 + bCol;

    float acc[4][8][4];
    #pragma unroll
    for (int mi = 0; mi < 4; mi++)
        #pragma unroll
        for (int nj = 0; nj < 8; nj++)
            #pragma unroll
            for (int r = 0; r < 4; r++) acc[mi][nj][r] = 0.f;

    const int nIter = K / 32;

    #pragma unroll
    for (int s = 0; s < 2; s++) {
        float* as = smem + s * STG;
        float* bs = smem + s * STG + ABUF;
        #pragma unroll
        for (int i = 0; i < 8; i++)
            cp16(as + (aRow + i * 16) * ASTRIDE + aCol,
                 Ag + (size_t)(i * 16) * K + s * 32);
        #pragma unroll
        for (int i = 0; i < 8; i++)
            cp16(bs + bRow * BSTRIDE + bCol + i * 16,
                 Bg + (size_t)(s * 32) * N + i * 16);
        cp_commit();
    }

    for (int t = 0; t < nIter; t++) {
        cp_wait1();
        __syncthreads();

        if (t + 2 < nIter) {
            int s = (t + 2) % 3;
            int k0 = (t + 2) * 32;
            float* as = smem + s * STG;
            float* bs = smem + s * STG + ABUF;
            #pragma unroll
            for (int i = 0; i < 8; i++)
                cp16(as + (aRow + i * 16) * ASTRIDE + aCol,
                     Ag + (size_t)(i * 16) * K + k0);
            #pragma unroll
            for (int i = 0; i < 8; i++)
                cp16(bs + bRow * BSTRIDE + bCol + i * 16,
                     Bg + (size_t)k0 * N + i * 16);
            cp_commit();
        }

        const float* ab = smem + (t % 3) * STG;
        const float* bb = ab + ABUF;
        #pragma unroll
        for (int ks = 0; ks < 4; ks++) {
            int k8 = ks * 8;
            uint32_t af[4][4], bf[8][2];
            #pragma unroll
            for (int mi = 0; mi < 4; mi++) {
                const float* p = ab + (wm + mi * 16 + g) * ASTRIDE + k8 + l;
                af[mi][0] = __float_as_uint(p[0]);
                af[mi][1] = __float_as_uint(p[8 * ASTRIDE]);
                af[mi][2] = __float_as_uint(p[4]);
                af[mi][3] = __float_as_uint(p[8 * ASTRIDE + 4]);
            }
            #pragma unroll
            for (int nj = 0; nj < 8; nj++) {
                const float* p = bb + (k8 + l) * BSTRIDE + wn + nj * 8 + g;
                bf[nj][0] = __float_as_uint(p[0]);
                bf[nj][1] = __float_as_uint(p[4 * BSTRIDE]);
            }
            #pragma unroll
            for (int mi = 0; mi < 4; mi++)
                #pragma unroll
                for (int nj = 0; nj < 8; nj++)
                    mma_tf32(acc[mi][nj], af[mi], bf[nj]);
        }
    }

    int row0 = by * 128 + wm;
    int col0 = nx * 128 + wn;
    bool rope = (mat < 2);
    #pragma unroll
    for (int mi = 0; mi < 4; mi++) {
        int r = row0 + mi * 16 + g;
        int t0 = r & (SEQ - 1);
        #pragma unroll
        for (int nj = 0; nj < 8; nj++) {
            int cc = col0 + nj * 8 + 2 * l;
            float v0 = acc[mi][nj][0], v1 = acc[mi][nj][1];
            float v2 = acc[mi][nj][2], v3 = acc[mi][nj][3];
            if (rope) {
                int pi = (cc & 63) >> 1;
                float invf = exp2f(-0.41524101186f * (float)pi);
                float a0 = (float)t0 * invf;
                float a1 = (float)(t0 + 8) * invf;
                float c0, s0, c1, s1;
                sincosf(a0, &s0, &c0);
                sincosf(a1, &s1, &c1);
                float n0 = v0 * c0 - v1 * s0;
                float n1 = v1 * c0 + v0 * s0;
                float n2 = v2 * c1 - v3 * s1;
                float n3 = v3 * c1 + v2 * s1;
                v0 = n0; v1 = n1; v2 = n2; v3 = n3;
            }
            *(float2*)&C[(size_t)r * D_MODEL + cc] = make_float2(v0, v1);
            *(float2*)&C[(size_t)(r + 8) * D_MODEL + cc] = make_float2(v2, v3);
        }
    }
}

// ---------------- MMA flash attention (tf32) — passing R16 version ----------------
#define KSTR 68
#define ATT_SMEM ((64 * KSTR + 64 * KSTR + 128 * KSTR) * 4)

__global__ __launch_bounds__(256) void attn_mma(const float* __restrict__ q,
                                                const float* __restrict__ k,
                                                const float* __restrict__ v,
                                                float* __restrict__ out) {
    extern __shared__ float sm[];
    float* Ks = sm;
    float* Vs = sm + 64 * KSTR;
    float* Ps = sm + 128 * KSTR;

    int tid = threadIdx.x;
    int lane = tid & 31, wid = tid >> 5;
    int g = lane >> 2, l = lane & 3;
    int wm = wid * 16;

    int qtile = blockIdx.x;
    int bh = blockIdx.y;
    int b = bh >> 4, h = bh & 15;
    int hoff = h * HEAD_DIM;
    int qrow0 = b * SEQ + qtile * 128;

    for (int i = tid; i < 128 * 16; i += 256) {
        int r = i >> 4, d4 = (i & 15) * 4;
        float4 qv = *(const float4*)(q + (size_t)(qrow0 + r) * D_MODEL + hoff + d4);
        float4 t;
        t.x = to_tf32(qv.x * 0.125f); t.y = to_tf32(qv.y * 0.125f);
        t.z = to_tf32(qv.z * 0.125f); t.w = to_tf32(qv.w * 0.125f);
        *(float4*)(Ps + r * KSTR + d4) = t;
    }
    __syncthreads();
    uint32_t qf[8][4];
    #pragma unroll
    for (int ks = 0; ks < 8; ks++) {
        const float* p = Ps + (wm + g) * KSTR + ks * 8 + l;
        qf[ks][0] = __float_as_uint(p[0]);
        qf[ks][1] = __float_as_uint(p[8 * KSTR]);
        qf[ks][2] = __float_as_uint(p[4]);
        qf[ks][3] = __float_as_uint(p[8 * KSTR + 4]);
    }

    float oa[8][4];
    #pragma unroll
    for (int nj = 0; nj < 8; nj++)
        #pragma unroll
        for (int r = 0; r < 4; r++) oa[nj][r] = 0.f;
    float m0 = -1e30f, m1 = -1e30f, ls0 = 0.f, ls1 = 0.f;

    for (int kt = 0; kt < SEQ / 64; kt++) {
        __syncthreads();
        for (int i = tid; i < 64 * 16; i += 256) {
            int r = i >> 4, d4 = (i & 15) * 4;
            size_t gi = (size_t)(b * SEQ + kt * 64 + r) * D_MODEL + hoff + d4;
            float4 kv = *(const float4*)(k + gi);
            float4 tk;
            tk.x = to_tf32(kv.x); tk.y = to_tf32(kv.y);
            tk.z = to_tf32(kv.z); tk.w = to_tf32(kv.w);
            *(float4*)(Ks + r * KSTR + d4) = tk;
            float4 vv = *(const float4*)(v + gi);
            float4 tv;
            tv.x = to_tf32(vv.x); tv.y = to_tf32(vv.y);
            tv.z = to_tf32(vv.z); tv.w = to_tf32(vv.w);
            *(float4*)(Vs + r * KSTR + d4) = tv;
        }
        __syncthreads();

        float sa[8][4];
        #pragma unroll
        for (int nj = 0; nj < 8; nj++)
            #pragma unroll
            for (int r = 0; r < 4; r++) sa[nj][r] = 0.f;
        #pragma unroll
        for (int ks = 0; ks < 8; ks++) {
            int k8 = ks * 8;
            #pragma unroll
            for (int nj = 0; nj < 8; nj++) {
                const float* p = Ks + (nj * 8 + g) * KSTR + k8 + l;
                uint32_t bf[2];
                bf[0] = __float_as_uint(p[0]);
                bf[1] = __float_as_uint(p[4]);
                mma_tf32(sa[nj], qf[ks], bf);
            }
        }

        float mx0 = -1e30f, mx1 = -1e30f;
        #pragma unroll
        for (int nj = 0; nj < 8; nj++) {
            mx0 = fmaxf(mx0, fmaxf(sa[nj][0], sa[nj][1]));
            mx1 = fmaxf(mx1, fmaxf(sa[nj][2], sa[nj][3]));
        }
        mx0 = fmaxf(mx0, __shfl_xor_sync(0xffffffffu, mx0, 1));
        mx0 = fmaxf(mx0, __shfl_xor_sync(0xffffffffu, mx0, 2));
        mx1 = fmaxf(mx1, __shfl_xor_sync(0xffffffffu, mx1, 1));
        mx1 = fmaxf(mx1, __shfl_xor_sync(0xffffffffu, mx1, 2));
        float nm0 = fmaxf(m0, mx0), nm1 = fmaxf(m1, mx1);
        float sc0 = __expf(m0 - nm0), sc1 = __expf(m1 - nm1);
        m0 = nm0; m1 = nm1;
        ls0 *= sc0; ls1 *= sc1;
        #pragma unroll
        for (int nj = 0; nj < 8; nj++) {
            oa[nj][0] *= sc0; oa[nj][1] *= sc0;
            oa[nj][2] *= sc1; oa[nj][3] *= sc1;
        }

        float* pw0 = Ps + (wm + g) * KSTR + 2 * l;
        float* pw1 = Ps + (wm + g + 8) * KSTR + 2 * l;
        #pragma unroll
        for (int nj = 0; nj < 8; nj++) {
            float p0 = __expf(sa[nj][0] - m0);
            float p1 = __expf(sa[nj][1] - m0);
            float p2 = __expf(sa[nj][2] - m1);
            float p3 = __expf(sa[nj][3] - m1);
            ls0 += p0 + p1;
            ls1 += p2 + p3;
            *(float2*)(pw0 + nj * 8) = make_float2(to_tf32(p0), to_tf32(p1));
            *(float2*)(pw1 + nj * 8) = make_float2(to_tf32(p2), to_tf32(p3));
        }
        __syncwarp();

        #pragma unroll
        for (int ks = 0; ks < 8; ks++) {
            int k8 = ks * 8;
            uint32_t pf[4];
            const float* pp = Ps + (wm + g) * KSTR + k8 + l;
            pf[0] = __float_as_uint(pp[0]);
            pf[1] = __float_as_uint(pp[8 * KSTR]);
            pf[2] = __float_as_uint(pp[4]);
            pf[3] = __float_as_uint(pp[8 * KSTR + 4]);
            #pragma unroll
            for (int nj = 0; nj < 8; nj++) {
                const float* vp = Vs + (k8 + l) * KSTR + nj * 8 + g;
                uint32_t vf[2];
                vf[0] = __float_as_uint(vp[0]);
                vf[1] = __float_as_uint(vp[4 * KSTR]);
                mma_tf32(oa[nj], pf, vf);
            }
        }
    }

    ls0 += __shfl_xor_sync(0xffffffffu, ls0, 1);
    ls0 += __shfl_xor_sync(0xffffffffu, ls0, 2);
    ls1 += __shfl_xor_sync(0xffffffffu, ls1, 1);
    ls1 += __shfl_xor_sync(0xffffffffu, ls1, 2);
    float inv0 = 1.0f / ls0, inv1 = 1.0f / ls1;

    int r0 = qrow0 + wm + g;
    #pragma unroll
    for (int nj = 0; nj < 8; nj++) {
        int cc = hoff + nj * 8 + 2 * l;
        *(float2*)&out[(size_t)r0 * D_MODEL + cc] =
            make_float2(to_tf32(oa[nj][0] * inv0), to_tf32(oa[nj][1] * inv0));
        *(float2*)&out[(size_t)(r0 + 8) * D_MODEL + cc] =
            make_float2(to_tf32(oa[nj][2] * inv1), to_tf32(oa[nj][3] * inv1));
    }
}

// ---------------- launch ----------------
extern "C" void kernel_launch(void* const* d_in, const int* in_sizes, int n_in,
                              void* d_out, int out_size) {
    const float* inputs = (const float*)d_in[0];
    const float* ln1_g  = (const float*)d_in[1];
    const float* ln1_b  = (const float*)d_in[2];
    const float* Wq     = (const float*)d_in[3];
    const float* Wk     = (const float*)d_in[4];
    const float* Wv     = (const float*)d_in[5];
    const float* Wo     = (const float*)d_in[6];
    const float* ln2_g  = (const float*)d_in[7];
    const float* ln2_b  = (const float*)d_in[8];
    const float* Wfc2   = (const float*)d_in[9];
    const float* bfc2   = (const float*)d_in[10];
    const float* Wfc3   = (const float*)d_in[11];
    const float* bfc3   = (const float*)d_in[12];
    float* out = (float*)d_out;

    float *px, *pq, *pk, *pv, *patt, *pmlp, *pln2, *ph;
    float *rwq, *rwk, *rwv, *rwo, *rw2, *rw3;
    cudaGetSymbolAddress((void**)&px,   g_x);
    cudaGetSymbolAddress((void**)&pq,   g_q);
    cudaGetSymbolAddress((void**)&pk,   g_k);
    cudaGetSymbolAddress((void**)&pv,   g_v);
    cudaGetSymbolAddress((void**)&patt, g_att);
    cudaGetSymbolAddress((void**)&pmlp, g_mlpin);
    cudaGetSymbolAddress((void**)&pln2, g_ln2);
    cudaGetSymbolAddress((void**)&ph,   g_h);
    cudaGetSymbolAddress((void**)&rwq,  g_rwq);
    cudaGetSymbolAddress((void**)&rwk,  g_rwk);
    cudaGetSymbolAddress((void**)&rwv,  g_rwv);
    cudaGetSymbolAddress((void**)&rwo,  g_rwo);
    cudaGetSymbolAddress((void**)&rw2,  g_rw2);
    cudaGetSymbolAddress((void**)&rw3,  g_rw3);

    cudaFuncSetAttribute(gemm_tf32<1>, cudaFuncAttributeMaxDynamicSharedMemorySize, GEMM_SMEM);
    cudaFuncSetAttribute(gemm_tf32<2>, cudaFuncAttributeMaxDynamicSharedMemorySize, GEMM_SMEM);
    cudaFuncSetAttribute(gemm_tf32<3>, cudaFuncAttributeMaxDynamicSharedMemorySize, GEMM_SMEM);
    cudaFuncSetAttribute(qkv_gemm,     cudaFuncAttributeMaxDynamicSharedMemorySize, GEMM_SMEM);
    cudaFuncSetAttribute(attn_mma,     cudaFuncAttributeMaxDynamicSharedMemorySize, ATT_SMEM);

    // 0. round weights to tf32 (rna)
    int n1 = D_MODEL * D_MODEL / 4, n2 = D_MODEL * MLP_DIM / 4;
    round_w<<<(n1 + 255) / 256, 256>>>(Wq,   rwq, n1);
    round_w<<<(n1 + 255) / 256, 256>>>(Wk,   rwk, n1);
    round_w<<<(n1 + 255) / 256, 256>>>(Wv,   rwv, n1);
    round_w<<<(n1 + 255) / 256, 256>>>(Wo,   rwo, n1);
    round_w<<<(n2 + 255) / 256, 256>>>(Wfc2, rw2, n2);
    round_w<<<(n2 + 255) / 256, 256>>>(Wfc3, rw3, n2);

    // 1. x = LN1(inputs)  (tf32-rounded)
    ln_kernel<<<ROWS, 256>>>(inputs, ln1_g, ln1_b, px);

    // 2+3. fused QKV GEMM with RoPE epilogue
    qkv_gemm<<<dim3(24, ROWS / 128), 128, GEMM_SMEM>>>(px, rwq, rwk, rwv, pq, pk, pv);

    // 4. attention (tensor-core flash; tf32-rounded output)
    attn_mma<<<dim3(SEQ / 128, BATCH * NHEAD), 256, ATT_SMEM>>>(pq, pk, pv, patt);

    // 5. mlp_in = attn @ Wo + inputs
    gemm_tf32<1><<<dim3(D_MODEL / 128, ROWS / 128), 128, GEMM_SMEM>>>(
        patt, rwo, nullptr, inputs, pmlp, ROWS, D_MODEL, D_MODEL);

    // 6. ln2 (tf32-rounded)
    ln_kernel<<<ROWS, 256>>>(pmlp, ln2_g, ln2_b, pln2);

    // 7. h = gelu(ln2 @ Wfc2 + bfc2)  (tf32-rounded)
    gemm_tf32<2><<<dim3(MLP_DIM / 128, ROWS / 128), 128, GEMM_SMEM>>>(
        pln2, rw2, bfc2, nullptr, ph, ROWS, MLP_DIM, D_MODEL);

    // 8. out = h @ Wfc3 + bfc3 + mlp_in
    gemm_tf32<3><<<dim3(D_MODEL / 128, ROWS / 128), 128, GEMM_SMEM>>>(
        ph, rw3, bfc3, pmlp, out, ROWS, D_MODEL, MLP_DIM);
}